// round 2
// baseline (speedup 1.0000x reference)
#include <cuda_runtime.h>
#include <math.h>

#define NN   50000
#define EE   800000
#define DIN  128
#define D1   150
#define LD1  152
#define D2   100
#define LD2  112
#define DOUT 64
#define SCAN_B ((NN + 1023) / 1024)

// ---------------- scratch (static device globals; no allocation) ----------------
__device__ float g_deg_out[NN];
__device__ int   g_deg_in[NN];
__device__ int   g_off[NN + 1];
__device__ int   g_cur[NN];
__device__ int   g_bsum[SCAN_B];
__device__ int   g_bsum2[SCAN_B];
__device__ int   g_csr[EE];
__device__ float g_norm_out[NN];
__device__ float g_norm_in[NN];
__device__ float g_invdeg[NN];
__device__ __align__(16) float g_agg[(size_t)NN * DIN];     // layer-1 aggregate
__device__ __align__(16) float g_h1[(size_t)NN * LD1];      // elu(GraphConv), padded
__device__ __align__(16) float g_hWn[(size_t)NN * LD2];     // h1 @ Wn, padded
__device__ __align__(16) float g_neighWn[(size_t)NN * LD2]; // mean-aggregated hWn
__device__ __align__(16) float g_h2[(size_t)NN * LD2];      // elu(SAGE), padded

__device__ __forceinline__ float elu_f(float v) { return v > 0.f ? v : expm1f(v); }

__device__ __forceinline__ unsigned long long pack_dup(float x) {
    unsigned long long r;
    asm("mov.b64 %0, {%1, %1};" : "=l"(r) : "f"(x));
    return r;
}
__device__ __forceinline__ unsigned long long fma2(unsigned long long a,
                                                   unsigned long long b,
                                                   unsigned long long c) {
    unsigned long long d;
    asm("fma.rn.f32x2 %0, %1, %2, %3;" : "=l"(d) : "l"(a), "l"(b), "l"(c));
    return d;
}

// ---------------- graph preprocessing ----------------
__global__ void k_zero() {
    int i = blockIdx.x * blockDim.x + threadIdx.x;
    if (i < NN) { g_deg_out[i] = 0.f; g_deg_in[i] = 0; g_cur[i] = 0; }
}

__global__ void k_degrees(const int* __restrict__ src, const int* __restrict__ dst) {
    int e = blockIdx.x * blockDim.x + threadIdx.x;
    if (e >= EE) return;
    atomicAdd(&g_deg_out[src[e]], 1.f);
    atomicAdd(&g_deg_in[dst[e]], 1);
}

__global__ void k_norms() {
    int i = blockIdx.x * blockDim.x + threadIdx.x;
    if (i >= NN) return;
    float dof = g_deg_out[i];
    g_norm_out[i] = rsqrtf(fmaxf(dof, 1.f));
    float din = (float)g_deg_in[i];
    float dmx = fmaxf(din, 1.f);
    g_norm_in[i] = rsqrtf(dmx);
    g_invdeg[i]  = 1.f / dmx;
}

__global__ void k_scan1() {
    __shared__ int s[1024];
    int tid = threadIdx.x;
    int i = blockIdx.x * 1024 + tid;
    int v = (i < NN) ? g_deg_in[i] : 0;
    s[tid] = v;
    __syncthreads();
    for (int off = 1; off < 1024; off <<= 1) {
        int t = (tid >= off) ? s[tid - off] : 0;
        __syncthreads();
        s[tid] += t;
        __syncthreads();
    }
    if (i < NN) g_off[i + 1] = s[tid];
    if (tid == 1023) g_bsum[blockIdx.x] = s[1023];
}

__global__ void k_scan2() {
    if (threadIdx.x == 0 && blockIdx.x == 0) {
        int acc = 0;
        for (int b = 0; b < SCAN_B; b++) { g_bsum2[b] = acc; acc += g_bsum[b]; }
    }
}

__global__ void k_scan3() {
    int tid = threadIdx.x;
    int i = blockIdx.x * 1024 + tid;
    if (i < NN && blockIdx.x > 0) g_off[i + 1] += g_bsum2[blockIdx.x];
    if (i == 0) g_off[0] = 0;
}

__global__ void k_fill(const int* __restrict__ src, const int* __restrict__ dst) {
    int e = blockIdx.x * blockDim.x + threadIdx.x;
    if (e >= EE) return;
    int d = dst[e];
    int p = atomicAdd(&g_cur[d], 1);
    g_csr[g_off[d] + p] = src[e];
}

// ---------------- layer-1 aggregation (pull, 1 warp / node, D_IN=128) ----------------
__global__ void k_agg1(const float* __restrict__ x) {
    int w    = (blockIdx.x * blockDim.x + threadIdx.x) >> 5;
    int lane = threadIdx.x & 31;
    if (w >= NN) return;
    int beg = g_off[w], end = g_off[w + 1];
    const float4* X = (const float4*)x;
    float4 acc = make_float4(0.f, 0.f, 0.f, 0.f);
    int j = beg;
    for (; j + 1 < end; j += 2) {
        int s0 = g_csr[j], s1 = g_csr[j + 1];
        float w0 = g_norm_out[s0], w1 = g_norm_out[s1];
        float4 v0 = X[(size_t)s0 * 32 + lane];
        float4 v1 = X[(size_t)s1 * 32 + lane];
        acc.x += v0.x * w0 + v1.x * w1;
        acc.y += v0.y * w0 + v1.y * w1;
        acc.z += v0.z * w0 + v1.z * w1;
        acc.w += v0.w * w0 + v1.w * w1;
    }
    if (j < end) {
        int s0 = g_csr[j];
        float w0 = g_norm_out[s0];
        float4 v0 = X[(size_t)s0 * 32 + lane];
        acc.x += v0.x * w0; acc.y += v0.y * w0; acc.z += v0.z * w0; acc.w += v0.w * w0;
    }
    float ni = g_norm_in[w];
    acc.x *= ni; acc.y *= ni; acc.z *= ni; acc.w *= ni;
    ((float4*)g_agg)[(size_t)w * 32 + lane] = acc;
}

// ---------------- layer-2 aggregation over hWn (112 padded cols, 28 float4) --------
__global__ void k_agg2() {
    int w    = (blockIdx.x * blockDim.x + threadIdx.x) >> 5;
    int lane = threadIdx.x & 31;
    if (w >= NN) return;
    if (lane >= LD2 / 4) return;
    int beg = g_off[w], end = g_off[w + 1];
    const float4* X = (const float4*)g_hWn;
    float4 acc = make_float4(0.f, 0.f, 0.f, 0.f);
    int j = beg;
    for (; j + 1 < end; j += 2) {
        int s0 = g_csr[j], s1 = g_csr[j + 1];
        float4 v0 = X[(size_t)s0 * (LD2 / 4) + lane];
        float4 v1 = X[(size_t)s1 * (LD2 / 4) + lane];
        acc.x += v0.x + v1.x; acc.y += v0.y + v1.y;
        acc.z += v0.z + v1.z; acc.w += v0.w + v1.w;
    }
    if (j < end) {
        int s0 = g_csr[j];
        float4 v0 = X[(size_t)s0 * (LD2 / 4) + lane];
        acc.x += v0.x; acc.y += v0.y; acc.z += v0.z; acc.w += v0.w;
    }
    float inv = g_invdeg[w];
    acc.x *= inv; acc.y *= inv; acc.z *= inv; acc.w *= inv;
    ((float4*)g_neighWn)[(size_t)w * (LD2 / 4) + lane] = acc;
}

// ---------------- f32x2 double-buffered GEMM ----------------
// C[M, ldc] = epi( A[M, lda(=K)] @ B[KB, NB] + bias + C0 ), tile 128 x (4*NTH)
template<int NTH, bool HAS_EPI, bool HAS_C0>
__global__ void k_gemm(const float* __restrict__ A,
                       const float* __restrict__ B, int KB, int NB,
                       const float* __restrict__ bias,
                       const float* __restrict__ C0, int ldc0,
                       float* __restrict__ C, int ldc, int M, int lda)
{
    constexpr int T  = NTH * 16;
    constexpr int NT = NTH * 4;
    __shared__ __align__(16) float As[2][16][128];
    __shared__ __align__(16) float Bs[2][16][NT];

    int t  = threadIdx.x;
    int ty = t & 15;        // M micro index
    int tx = t >> 4;        // N micro index (0..NTH-1)
    int m0 = blockIdx.y * 128, n0 = blockIdx.x * NT;
    int K  = lda;           // A padded so lda == K_iter (multiple of 16)

    float4 ra[2];
    float  rb[4];

    // prologue load of slice 0
    {
        int k0 = 0;
#pragma unroll
        for (int i = 0; i < 2; i++) {
            int idx = t + T * i;
            if (idx < 512) {
                int mm = idx >> 2, kq = (idx & 3) * 4;
                int gm = m0 + mm;
                ra[i] = (gm < M) ? *(const float4*)(A + (size_t)gm * lda + k0 + kq)
                                 : make_float4(0.f, 0.f, 0.f, 0.f);
            }
        }
#pragma unroll
        for (int i = 0; i < 4; i++) {
            int idx = t + T * i;
            int kk = idx / NT, nn = idx % NT;
            int gk = k0 + kk, gn = n0 + nn;
            rb[i] = (gk < KB && gn < NB) ? B[(size_t)gk * NB + gn] : 0.f;
        }
    }

    unsigned long long acc[4][4] = {};
    int buf = 0;

    for (int k0 = 0; k0 < K; k0 += 16) {
        // stage regs -> smem
#pragma unroll
        for (int i = 0; i < 2; i++) {
            int idx = t + T * i;
            if (idx < 512) {
                int mm = idx >> 2, kq = (idx & 3) * 4;
                As[buf][kq + 0][mm] = ra[i].x;
                As[buf][kq + 1][mm] = ra[i].y;
                As[buf][kq + 2][mm] = ra[i].z;
                As[buf][kq + 3][mm] = ra[i].w;
            }
        }
#pragma unroll
        for (int i = 0; i < 4; i++) {
            int idx = t + T * i;
            int kk = idx / NT, nn = idx % NT;
            Bs[buf][kk][nn] = rb[i];
        }
        __syncthreads();

        // prefetch next slice
        if (k0 + 16 < K) {
            int kn = k0 + 16;
#pragma unroll
            for (int i = 0; i < 2; i++) {
                int idx = t + T * i;
                if (idx < 512) {
                    int mm = idx >> 2, kq = (idx & 3) * 4;
                    int gm = m0 + mm;
                    ra[i] = (gm < M) ? *(const float4*)(A + (size_t)gm * lda + kn + kq)
                                     : make_float4(0.f, 0.f, 0.f, 0.f);
                }
            }
#pragma unroll
            for (int i = 0; i < 4; i++) {
                int idx = t + T * i;
                int kk = idx / NT, nn = idx % NT;
                int gk = kn + kk, gn = n0 + nn;
                rb[i] = (gk < KB && gn < NB) ? B[(size_t)gk * NB + gn] : 0.f;
            }
        }

        // compute on buf
#pragma unroll
        for (int kk = 0; kk < 16; kk++) {
            ulonglong2 a01 = *(const ulonglong2*)&As[buf][kk][ty * 8];
            ulonglong2 a23 = *(const ulonglong2*)&As[buf][kk][ty * 8 + 4];
            float4 bq = *(const float4*)&Bs[buf][kk][tx * 4];
            unsigned long long ap[4] = { a01.x, a01.y, a23.x, a23.y };
            unsigned long long bd[4] = { pack_dup(bq.x), pack_dup(bq.y),
                                         pack_dup(bq.z), pack_dup(bq.w) };
#pragma unroll
            for (int i = 0; i < 4; i++)
#pragma unroll
                for (int j = 0; j < 4; j++)
                    acc[i][j] = fma2(ap[i], bd[j], acc[i][j]);
        }
        buf ^= 1;
        __syncthreads();
    }

    // epilogue
    int gnb = n0 + tx * 4;
    float bv[4];
#pragma unroll
    for (int j = 0; j < 4; j++) {
        int gn = gnb + j;
        bv[j] = (HAS_EPI && bias != nullptr && gn < NB) ? bias[gn] : 0.f;
    }
#pragma unroll
    for (int i = 0; i < 4; i++) {
#pragma unroll
        for (int h = 0; h < 2; h++) {
            int gm = m0 + ty * 8 + 2 * i + h;
            if (gm >= M) continue;
            float4 vo;
            float* vp = &vo.x;
#pragma unroll
            for (int j = 0; j < 4; j++) {
                int gn = gnb + j;
                float2 p = *reinterpret_cast<float2*>(&acc[i][j]);
                float v = (h == 0) ? p.x : p.y;
                if (gn < NB) {
                    v += bv[j];
                    if (HAS_C0) v += C0[(size_t)gm * ldc0 + gn];
                    if (HAS_EPI) v = elu_f(v);
                } else {
                    v = 0.f;
                }
                vp[j] = v;
            }
            *(float4*)(C + (size_t)gm * ldc + gnb) = vo;
        }
    }
}

// ---------------- launch ----------------
extern "C" void kernel_launch(void* const* d_in, const int* in_sizes, int n_in,
                              void* d_out, int out_size) {
    const float* x   = (const float*)d_in[0];
    const int*   src = (const int*)d_in[1];
    const int*   dst = (const int*)d_in[2];
    const float* W1  = (const float*)d_in[3];
    const float* b1  = (const float*)d_in[4];
    const float* Wn  = (const float*)d_in[5];
    const float* Ws  = (const float*)d_in[6];
    const float* b2  = (const float*)d_in[7];
    const float* W3  = (const float*)d_in[8];
    const float* b3  = (const float*)d_in[9];
    float* out = (float*)d_out;

    float* agg    = nullptr; cudaGetSymbolAddress((void**)&agg,    g_agg);
    float* h1     = nullptr; cudaGetSymbolAddress((void**)&h1,     g_h1);
    float* hWn    = nullptr; cudaGetSymbolAddress((void**)&hWn,    g_hWn);
    float* neighW = nullptr; cudaGetSymbolAddress((void**)&neighW, g_neighWn);
    float* h2     = nullptr; cudaGetSymbolAddress((void**)&h2,     g_h2);

    k_zero<<<(NN + 255) / 256, 256>>>();
    k_degrees<<<(EE + 255) / 256, 256>>>(src, dst);
    k_norms<<<(NN + 255) / 256, 256>>>();
    k_scan1<<<SCAN_B, 1024>>>();
    k_scan2<<<1, 32>>>();
    k_scan3<<<SCAN_B, 1024>>>();
    k_fill<<<(EE + 255) / 256, 256>>>(src, dst);

    int agg_blocks = (NN * 32 + 255) / 256;
    k_agg1<<<agg_blocks, 256>>>(x);

    int MT = (NN + 127) / 128;  // 391

    // h1 = elu(agg @ W1 + b1)   [NN,150] stride 152, tiles 2x76
    k_gemm<19, true, false><<<dim3(2, MT), 304>>>(
        agg, W1, DIN, D1, b1, nullptr, 0, h1, LD1, NN, DIN);

    // hWn = h1 @ Wn             [NN,100] stride 112, tile 112
    k_gemm<28, false, false><<<dim3(1, MT), 448>>>(
        h1, Wn, D1, D2, nullptr, nullptr, 0, hWn, LD2, NN, LD1);

    // neighWn = mean-agg(hWn)
    k_agg2<<<agg_blocks, 256>>>();

    // h2 = elu(h1 @ Ws + neighWn + b2)
    k_gemm<28, true, true><<<dim3(1, MT), 448>>>(
        h1, Ws, D1, D2, b2, neighW, LD2, h2, LD2, NN, LD1);

    // out = elu(h2 @ W3 + b3)   [NN,64]
    k_gemm<16, true, false><<<dim3(1, MT), 256>>>(
        h2, W3, D2, DOUT, b3, nullptr, 0, out, DOUT, NN, LD2);
}

// round 5
// speedup vs baseline: 1.3522x; 1.3522x over previous
#include <cuda_runtime.h>
#include <cuda_bf16.h>
#include <math.h>
#include <stdint.h>

#define NN   50000
#define EE   800000
#define DIN  128
#define D1   150
#define KP1  192     // h1 K-padded
#define D2   100
#define LD2  112     // fp32 hWn/neighWn stride
#define KP2  128     // h2 K-padded
#define DOUT 64
#define SCAN_B ((NN + 1023) / 1024)

// ---------------- scratch ----------------
__device__ float g_deg_out[NN];
__device__ int   g_deg_in[NN];
__device__ int   g_off[NN + 1];
__device__ int   g_cur[NN];
__device__ int   g_bsum[SCAN_B];
__device__ int   g_bsum2[SCAN_B];
__device__ int   g_csr[EE];
__device__ float g_norm_out[NN];
__device__ float g_norm_in[NN];
__device__ float g_invdeg[NN];

__device__ __align__(16) __nv_bfloat16 g_aggh[(size_t)NN * DIN];
__device__ __align__(16) __nv_bfloat16 g_aggl[(size_t)NN * DIN];
__device__ __align__(16) __nv_bfloat16 g_h1h[(size_t)NN * KP1];
__device__ __align__(16) __nv_bfloat16 g_h1l[(size_t)NN * KP1];
__device__ __align__(16) __nv_bfloat16 g_h2h[(size_t)NN * KP2];
__device__ __align__(16) __nv_bfloat16 g_h2l[(size_t)NN * KP2];
__device__ __align__(16) float g_hWn[(size_t)NN * LD2];
__device__ __align__(16) float g_neighWn[(size_t)NN * LD2];

// weights transposed [NPAD, KPAD] bf16 hi/lo
__device__ __align__(16) __nv_bfloat16 g_B1h[192 * 128], g_B1l[192 * 128];
__device__ __align__(16) __nv_bfloat16 g_BWnh[128 * 192], g_BWnl[128 * 192];
__device__ __align__(16) __nv_bfloat16 g_BWsh[128 * 192], g_BWsl[128 * 192];
__device__ __align__(16) __nv_bfloat16 g_B3h[64 * 128],  g_B3l[64 * 128];

__device__ __forceinline__ float elu_f(float v) { return v > 0.f ? v : expm1f(v); }

__device__ __forceinline__ uint32_t smem_u32(const void* p) {
    uint32_t a;
    asm("{ .reg .u64 t; cvta.to.shared.u64 t, %1; cvt.u32.u64 %0, t; }" : "=r"(a) : "l"(p));
    return a;
}
__device__ __forceinline__ void ldsm_x4(uint32_t addr, uint32_t* r) {
    asm volatile("ldmatrix.sync.aligned.m8n8.x4.shared.b16 {%0,%1,%2,%3}, [%4];"
                 : "=r"(r[0]), "=r"(r[1]), "=r"(r[2]), "=r"(r[3]) : "r"(addr));
}
__device__ __forceinline__ void mma_bf16(float* d, const uint32_t* a, const uint32_t* b) {
    asm volatile("mma.sync.aligned.m16n8k16.row.col.f32.bf16.bf16.f32 "
                 "{%0,%1,%2,%3}, {%4,%5,%6,%7}, {%8,%9}, {%0,%1,%2,%3};"
                 : "+f"(d[0]), "+f"(d[1]), "+f"(d[2]), "+f"(d[3])
                 : "r"(a[0]), "r"(a[1]), "r"(a[2]), "r"(a[3]), "r"(b[0]), "r"(b[1]));
}

// ---------------- graph preprocessing ----------------
__global__ void k_zero() {
    int i = blockIdx.x * blockDim.x + threadIdx.x;
    if (i < NN) { g_deg_out[i] = 0.f; g_deg_in[i] = 0; g_cur[i] = 0; }
}
__global__ void k_degrees(const int* __restrict__ src, const int* __restrict__ dst) {
    int e = blockIdx.x * blockDim.x + threadIdx.x;
    if (e >= EE) return;
    atomicAdd(&g_deg_out[src[e]], 1.f);
    atomicAdd(&g_deg_in[dst[e]], 1);
}
__global__ void k_norms() {
    int i = blockIdx.x * blockDim.x + threadIdx.x;
    if (i >= NN) return;
    g_norm_out[i] = rsqrtf(fmaxf(g_deg_out[i], 1.f));
    float dmx = fmaxf((float)g_deg_in[i], 1.f);
    g_norm_in[i] = rsqrtf(dmx);
    g_invdeg[i]  = 1.f / dmx;
}
__global__ void k_scan1() {
    __shared__ int s[1024];
    int tid = threadIdx.x;
    int i = blockIdx.x * 1024 + tid;
    int v = (i < NN) ? g_deg_in[i] : 0;
    s[tid] = v;
    __syncthreads();
    for (int off = 1; off < 1024; off <<= 1) {
        int t = (tid >= off) ? s[tid - off] : 0;
        __syncthreads();
        s[tid] += t;
        __syncthreads();
    }
    if (i < NN) g_off[i + 1] = s[tid];
    if (tid == 1023) g_bsum[blockIdx.x] = s[1023];
}
__global__ void k_scan2() {
    if (threadIdx.x == 0 && blockIdx.x == 0) {
        int acc = 0;
        for (int b = 0; b < SCAN_B; b++) { g_bsum2[b] = acc; acc += g_bsum[b]; }
    }
}
__global__ void k_scan3() {
    int tid = threadIdx.x;
    int i = blockIdx.x * 1024 + tid;
    if (i < NN && blockIdx.x > 0) g_off[i + 1] += g_bsum2[blockIdx.x];
    if (i == 0) g_off[0] = 0;
}
__global__ void k_fill(const int* __restrict__ src, const int* __restrict__ dst) {
    int e = blockIdx.x * blockDim.x + threadIdx.x;
    if (e >= EE) return;
    int d = dst[e];
    int p = atomicAdd(&g_cur[d], 1);
    g_csr[g_off[d] + p] = src[e];
}

// ---------------- weight prep: W[KB,NB] -> bf16 hi/lo [NPADr,KPAD] ----------------
__global__ void k_wprep(const float* __restrict__ W, int KB, int NB,
                        __nv_bfloat16* __restrict__ bh, __nv_bfloat16* __restrict__ bl,
                        int NPADr, int KPAD) {
    int i = blockIdx.x * 256 + threadIdx.x;
    if (i >= NPADr * KPAD) return;
    int n = i / KPAD, k = i % KPAD;
    float v = (n < NB && k < KB) ? W[(size_t)k * NB + n] : 0.f;
    __nv_bfloat16 hv = __float2bfloat16(v);
    __nv_bfloat16 lv = __float2bfloat16(v - __bfloat162float(hv));
    bh[i] = hv; bl[i] = lv;
}

// ---------------- layer-1 aggregation -> bf16 hi/lo ----------------
__global__ void k_agg1(const float* __restrict__ x) {
    int w    = (blockIdx.x * blockDim.x + threadIdx.x) >> 5;
    int lane = threadIdx.x & 31;
    if (w >= NN) return;
    int beg = g_off[w], end = g_off[w + 1];
    const float4* X = (const float4*)x;
    float4 acc = make_float4(0.f, 0.f, 0.f, 0.f);
    int j = beg;
    for (; j + 1 < end; j += 2) {
        int s0 = g_csr[j], s1 = g_csr[j + 1];
        float w0 = g_norm_out[s0], w1 = g_norm_out[s1];
        float4 v0 = X[(size_t)s0 * 32 + lane];
        float4 v1 = X[(size_t)s1 * 32 + lane];
        acc.x += v0.x * w0 + v1.x * w1;
        acc.y += v0.y * w0 + v1.y * w1;
        acc.z += v0.z * w0 + v1.z * w1;
        acc.w += v0.w * w0 + v1.w * w1;
    }
    if (j < end) {
        int s0 = g_csr[j];
        float w0 = g_norm_out[s0];
        float4 v0 = X[(size_t)s0 * 32 + lane];
        acc.x += v0.x * w0; acc.y += v0.y * w0; acc.z += v0.z * w0; acc.w += v0.w * w0;
    }
    float ni = g_norm_in[w];
    float v[4] = { acc.x * ni, acc.y * ni, acc.z * ni, acc.w * ni };
    __nv_bfloat16 hv[4], lv[4];
#pragma unroll
    for (int q = 0; q < 4; q++) {
        hv[q] = __float2bfloat16(v[q]);
        lv[q] = __float2bfloat16(v[q] - __bfloat162float(hv[q]));
    }
    *(ushort4*)&g_aggh[(size_t)w * DIN + lane * 4] =
        make_ushort4(__bfloat16_as_ushort(hv[0]), __bfloat16_as_ushort(hv[1]),
                     __bfloat16_as_ushort(hv[2]), __bfloat16_as_ushort(hv[3]));
    *(ushort4*)&g_aggl[(size_t)w * DIN + lane * 4] =
        make_ushort4(__bfloat16_as_ushort(lv[0]), __bfloat16_as_ushort(lv[1]),
                     __bfloat16_as_ushort(lv[2]), __bfloat16_as_ushort(lv[3]));
}

// ---------------- layer-2 aggregation of hWn (fp32, 112 cols) ----------------
__global__ void k_agg2() {
    int w    = (blockIdx.x * blockDim.x + threadIdx.x) >> 5;
    int lane = threadIdx.x & 31;
    if (w >= NN) return;
    if (lane >= LD2 / 4) return;
    int beg = g_off[w], end = g_off[w + 1];
    const float4* X = (const float4*)g_hWn;
    float4 acc = make_float4(0.f, 0.f, 0.f, 0.f);
    int j = beg;
    for (; j + 1 < end; j += 2) {
        int s0 = g_csr[j], s1 = g_csr[j + 1];
        float4 v0 = X[(size_t)s0 * (LD2 / 4) + lane];
        float4 v1 = X[(size_t)s1 * (LD2 / 4) + lane];
        acc.x += v0.x + v1.x; acc.y += v0.y + v1.y;
        acc.z += v0.z + v1.z; acc.w += v0.w + v1.w;
    }
    if (j < end) {
        int s0 = g_csr[j];
        float4 v0 = X[(size_t)s0 * (LD2 / 4) + lane];
        acc.x += v0.x; acc.y += v0.y; acc.z += v0.z; acc.w += v0.w;
    }
    float inv = g_invdeg[w];
    acc.x *= inv; acc.y *= inv; acc.z *= inv; acc.w *= inv;
    ((float4*)g_neighWn)[(size_t)w * (LD2 / 4) + lane] = acc;
}

// ---------------- mma.sync bf16-split GEMM ----------------
// D = Ahi.Bhi + Ahi.Blo + Alo.Bhi; block 128M x 64N, 8 warps (4Mx2N), warp 32x32
template<int NPAD, int KPAD, bool HAS_EPI, bool HAS_C0, bool OUT_SPLIT>
__global__ void __launch_bounds__(256) k_mm(
    const __nv_bfloat16* __restrict__ Ah, const __nv_bfloat16* __restrict__ Al,
    int lda, int M,
    const __nv_bfloat16* __restrict__ Bh, const __nv_bfloat16* __restrict__ Bl,
    const float* __restrict__ bias, int NB,
    const float* __restrict__ C0, int ldc0,
    float* __restrict__ Of, __nv_bfloat16* __restrict__ Oh,
    __nv_bfloat16* __restrict__ Ol, int ldo)
{
    constexpr int CPP = KPAD / 32;   // 32-k chunks per phase
    constexpr int NC  = 3 * CPP;
    // layout: [A0:10240][A1:10240][B0:5120][B1:5120]; rows padded to 40 bf16 (80B)
    __shared__ __align__(16) char smem[30720];

    int t = threadIdx.x, lane = t & 31, wid = t >> 5;
    int wm = wid & 3, wn = wid >> 2;
    int m0 = blockIdx.y * 128, n0 = blockIdx.x * 64;

    uint32_t sbase = smem_u32(smem);
    int tile = lane >> 3, trow = lane & 7;
    // A ldsm base: tiles (m0-7,k0),(m8-15,k0),(m0-7,k8),(m8-15,k8)
    uint32_t aAddr = sbase + (uint32_t)(((wm * 32 + (tile & 1) * 8 + trow) * 40 +
                                         (tile >> 1) * 8) * 2);
    // B ldsm base: tiles (n0-7,k0),(n0-7,k8),(n8-15,k0),(n8-15,k8)
    uint32_t bAddr = sbase + 20480u + (uint32_t)(((wn * 32 + (tile >> 1) * 8 + trow) * 40 +
                                                  (tile & 1) * 8) * 2);

    float d[2][4][4];
#pragma unroll
    for (int i = 0; i < 2; i++)
#pragma unroll
        for (int j = 0; j < 4; j++)
#pragma unroll
            for (int q = 0; q < 4; q++) d[i][j][q] = 0.f;

    uint4 ra[2], rb[2];
    int mload = m0 + (t >> 1); if (mload >= M) mload = M - 1;
    int nload = n0 + (t >> 1);

    auto ldregs = [&](int cc) {
        int ph = cc / CPP, kc = cc - ph * CPP, k0 = kc * 32;
        const __nv_bfloat16* Ap = (ph == 2) ? Al : Ah;
        const __nv_bfloat16* Bp = (ph == 1) ? Bl : Bh;
        const char* ap = (const char*)(Ap + (size_t)mload * lda + k0) + (t & 1) * 16;
        ra[0] = *(const uint4*)ap;
        ra[1] = *(const uint4*)(ap + 32);
        if (t < 128) {
            const char* bp = (const char*)(Bp + (size_t)nload * KPAD + k0) + (t & 1) * 16;
            rb[0] = *(const uint4*)bp;
            rb[1] = *(const uint4*)(bp + 32);
        }
    };

    ldregs(0);
    int buf = 0;
#pragma unroll 1
    for (int cc = 0; cc < NC; cc++) {
        // regs -> smem
        {
            char* sa = smem + buf * 10240 + ((t >> 1) * 40) * 2 + (t & 1) * 16;
            *(uint4*)sa = ra[0];
            *(uint4*)(sa + 32) = ra[1];
            if (t < 128) {
                char* sb = smem + 20480 + buf * 5120 + ((t >> 1) * 40) * 2 + (t & 1) * 16;
                *(uint4*)sb = rb[0];
                *(uint4*)(sb + 32) = rb[1];
            }
        }
        __syncthreads();
        if (cc + 1 < NC) ldregs(cc + 1);
        // compute 2 k16 steps
        uint32_t offA = buf * 10240, offB = buf * 5120;
#pragma unroll
        for (int kk = 0; kk < 2; kk++) {
            uint32_t a[2][4], b[2][4];
            ldsm_x4(aAddr + offA + kk * 32, a[0]);
            ldsm_x4(aAddr + offA + 1280 + kk * 32, a[1]);
            ldsm_x4(bAddr + offB + kk * 32, b[0]);
            ldsm_x4(bAddr + offB + 1280 + kk * 32, b[1]);
#pragma unroll
            for (int mf = 0; mf < 2; mf++)
#pragma unroll
                for (int nf = 0; nf < 4; nf++)
                    mma_bf16(d[mf][nf], a[mf], &b[nf >> 1][(nf & 1) * 2]);
        }
        buf ^= 1;
        __syncthreads();
    }

    // ---------------- epilogue ----------------
    int rbase = lane >> 2, cpair = (lane & 3) * 2;
    float bv[4][2];
#pragma unroll
    for (int nf = 0; nf < 4; nf++) {
        int c = n0 + wn * 32 + nf * 8 + cpair;
        bv[nf][0] = (HAS_EPI && c < NB) ? bias[c] : 0.f;
        bv[nf][1] = (HAS_EPI && c + 1 < NB) ? bias[c + 1] : 0.f;
    }
#pragma unroll
    for (int mf = 0; mf < 2; mf++) {
#pragma unroll
        for (int h = 0; h < 2; h++) {
            int m = m0 + wm * 32 + mf * 16 + h * 8 + rbase;
            if (m >= M) continue;
#pragma unroll
            for (int nf = 0; nf < 4; nf++) {
                int c = n0 + wn * 32 + nf * 8 + cpair;
                float v0 = d[mf][nf][h * 2 + 0] + bv[nf][0];
                float v1 = d[mf][nf][h * 2 + 1] + bv[nf][1];
                if (HAS_C0) {
                    if (c < ldc0)     v0 += C0[(size_t)m * ldc0 + c];
                    if (c + 1 < ldc0) v1 += C0[(size_t)m * ldc0 + c + 1];
                }
                if (HAS_EPI) { v0 = elu_f(v0); v1 = elu_f(v1); }
                if (OUT_SPLIT) {
                    __nv_bfloat16 h0 = __float2bfloat16(v0);
                    __nv_bfloat16 h1v = __float2bfloat16(v1);
                    __nv_bfloat16 l0 = __float2bfloat16(v0 - __bfloat162float(h0));
                    __nv_bfloat16 l1 = __float2bfloat16(v1 - __bfloat162float(h1v));
                    *(ushort2*)&Oh[(size_t)m * ldo + c] =
                        make_ushort2(__bfloat16_as_ushort(h0), __bfloat16_as_ushort(h1v));
                    *(ushort2*)&Ol[(size_t)m * ldo + c] =
                        make_ushort2(__bfloat16_as_ushort(l0), __bfloat16_as_ushort(l1));
                } else {
                    if (c + 1 < ldo + 1 && c < ldo) {
                        *(float2*)&Of[(size_t)m * ldo + c] = make_float2(v0, v1);
                    }
                }
            }
        }
    }
}

// ---------------- launch ----------------
extern "C" void kernel_launch(void* const* d_in, const int* in_sizes, int n_in,
                              void* d_out, int out_size) {
    const float* x   = (const float*)d_in[0];
    const int*   src = (const int*)d_in[1];
    const int*   dst = (const int*)d_in[2];
    const float* W1  = (const float*)d_in[3];
    const float* b1  = (const float*)d_in[4];
    const float* Wn  = (const float*)d_in[5];
    const float* Ws  = (const float*)d_in[6];
    const float* b2  = (const float*)d_in[7];
    const float* W3  = (const float*)d_in[8];
    const float* b3  = (const float*)d_in[9];
    float* out = (float*)d_out;

    auto sym = [](const void* s) { void* p = nullptr; cudaGetSymbolAddress(&p, s); return p; };
    __nv_bfloat16* aggh = (__nv_bfloat16*)sym(g_aggh);
    __nv_bfloat16* aggl = (__nv_bfloat16*)sym(g_aggl);
    __nv_bfloat16* h1h  = (__nv_bfloat16*)sym(g_h1h);
    __nv_bfloat16* h1l  = (__nv_bfloat16*)sym(g_h1l);
    __nv_bfloat16* h2h  = (__nv_bfloat16*)sym(g_h2h);
    __nv_bfloat16* h2l  = (__nv_bfloat16*)sym(g_h2l);
    float* hWn    = (float*)sym(g_hWn);
    float* neighW = (float*)sym(g_neighWn);
    __nv_bfloat16* B1h  = (__nv_bfloat16*)sym(g_B1h),  *B1l  = (__nv_bfloat16*)sym(g_B1l);
    __nv_bfloat16* BWnh = (__nv_bfloat16*)sym(g_BWnh), *BWnl = (__nv_bfloat16*)sym(g_BWnl);
    __nv_bfloat16* BWsh = (__nv_bfloat16*)sym(g_BWsh), *BWsl = (__nv_bfloat16*)sym(g_BWsl);
    __nv_bfloat16* B3h  = (__nv_bfloat16*)sym(g_B3h),  *B3l  = (__nv_bfloat16*)sym(g_B3l);

    k_zero<<<(NN + 255) / 256, 256>>>();
    k_degrees<<<(EE + 255) / 256, 256>>>(src, dst);
    k_norms<<<(NN + 255) / 256, 256>>>();
    k_scan1<<<SCAN_B, 1024>>>();
    k_scan2<<<1, 32>>>();
    k_scan3<<<SCAN_B, 1024>>>();
    k_fill<<<(EE + 255) / 256, 256>>>(src, dst);

    k_wprep<<<(192 * 128 + 255) / 256, 256>>>(W1, DIN, D1, B1h, B1l, 192, 128);
    k_wprep<<<(128 * 192 + 255) / 256, 256>>>(Wn, D1, D2, BWnh, BWnl, 128, 192);
    k_wprep<<<(128 * 192 + 255) / 256, 256>>>(Ws, D1, D2, BWsh, BWsl, 128, 192);
    k_wprep<<<(64 * 128 + 255) / 256, 256>>>(W3, D2, DOUT, B3h, B3l, 64, 128);

    int agg_blocks = (NN * 32 + 255) / 256;
    k_agg1<<<agg_blocks, 256>>>(x);

    int MT = (NN + 127) / 128;  // 391

    // h1 = elu(agg @ W1 + b1) -> bf16 hi/lo [NN, 192]
    k_mm<192, 128, true, false, true><<<dim3(3, MT), 256>>>(
        aggh, aggl, DIN, NN, B1h, B1l, b1, D1,
        nullptr, 0, nullptr, h1h, h1l, KP1);

    // hWn = h1 @ Wn -> fp32 [NN, 112]
    k_mm<128, 192, false, false, false><<<dim3(2, MT), 256>>>(
        h1h, h1l, KP1, NN, BWnh, BWnl, nullptr, 0,
        nullptr, 0, hWn, nullptr, nullptr, LD2);

    k_agg2<<<agg_blocks, 256>>>();

    // h2 = elu(h1 @ Ws + neighWn + b2) -> bf16 hi/lo [NN, 128]
    k_mm<128, 192, true, true, true><<<dim3(2, MT), 256>>>(
        h1h, h1l, KP1, NN, BWsh, BWsl, b2, D2,
        neighW, LD2, nullptr, h2h, h2l, KP2);

    // out = elu(h2 @ W3 + b3) -> fp32 [NN, 64]
    k_mm<64, 128, true, false, false><<<dim3(1, MT), 256>>>(
        h2h, h2l, KP2, NN, B3h, B3l, b3, DOUT,
        nullptr, 0, out, nullptr, nullptr, DOUT);
}

// round 6
// speedup vs baseline: 1.4919x; 1.1033x over previous
#include <cuda_runtime.h>
#include <cuda_bf16.h>
#include <math.h>
#include <stdint.h>

#define NN   50000
#define EE   800000
#define DIN  128
#define D1   150
#define KP1  160     // h1 K-padded (5 chunks of 32)
#define D2   100
#define LD2  100     // fp32 hWn/neighWn stride
#define KP2  128     // h2 K-padded
#define DOUT 64
#define SCAN_B ((NN + 1023) / 1024)

// ---------------- scratch ----------------
__device__ float g_deg_out[NN];
__device__ int   g_deg_in[NN];
__device__ int   g_off[NN + 1];
__device__ int   g_cur[NN];
__device__ int   g_pref[SCAN_B];
__device__ int   g_csr[EE];
__device__ float g_norm_out[NN];
__device__ float g_norm_in[NN];
__device__ float g_invdeg[NN];

__device__ __align__(16) __nv_bfloat16 g_aggh[(size_t)NN * DIN];
__device__ __align__(16) __nv_bfloat16 g_aggl[(size_t)NN * DIN];
__device__ __align__(16) __nv_bfloat16 g_h1h[(size_t)NN * KP1];
__device__ __align__(16) __nv_bfloat16 g_h1l[(size_t)NN * KP1];
__device__ __align__(16) __nv_bfloat16 g_h2h[(size_t)NN * KP2];
__device__ __align__(16) __nv_bfloat16 g_h2l[(size_t)NN * KP2];
__device__ __align__(16) float g_hWn[(size_t)NN * LD2];
__device__ __align__(16) float g_neighWn[(size_t)NN * LD2];

// weights transposed [NPAD, KPAD] bf16 hi/lo
__device__ __align__(16) __nv_bfloat16 g_B1h[160 * 128], g_B1l[160 * 128];
__device__ __align__(16) __nv_bfloat16 g_BWnh[128 * 160], g_BWnl[128 * 160];
__device__ __align__(16) __nv_bfloat16 g_BWsh[128 * 160], g_BWsl[128 * 160];
__device__ __align__(16) __nv_bfloat16 g_B3h[64 * 128],  g_B3l[64 * 128];

__device__ __forceinline__ float elu_f(float v) { return v > 0.f ? v : expm1f(v); }

__device__ __forceinline__ uint32_t smem_u32(const void* p) {
    uint32_t a;
    asm("{ .reg .u64 t; cvta.to.shared.u64 t, %1; cvt.u32.u64 %0, t; }" : "=r"(a) : "l"(p));
    return a;
}
__device__ __forceinline__ void ldsm_x4(uint32_t addr, uint32_t* r) {
    asm volatile("ldmatrix.sync.aligned.m8n8.x4.shared.b16 {%0,%1,%2,%3}, [%4];"
                 : "=r"(r[0]), "=r"(r[1]), "=r"(r[2]), "=r"(r[3]) : "r"(addr));
}
__device__ __forceinline__ void mma_bf16(float* d, const uint32_t* a, const uint32_t* b) {
    asm volatile("mma.sync.aligned.m16n8k16.row.col.f32.bf16.bf16.f32 "
                 "{%0,%1,%2,%3}, {%4,%5,%6,%7}, {%8,%9}, {%0,%1,%2,%3};"
                 : "+f"(d[0]), "+f"(d[1]), "+f"(d[2]), "+f"(d[3])
                 : "r"(a[0]), "r"(a[1]), "r"(a[2]), "r"(a[3]), "r"(b[0]), "r"(b[1]));
}

// ---------------- preprocessing ----------------
__global__ void k_zero() {
    int i = blockIdx.x * blockDim.x + threadIdx.x;
    if (i < NN) { g_deg_out[i] = 0.f; g_deg_in[i] = 0; g_cur[i] = 0; }
    if (i < SCAN_B) g_pref[i] = 0;
}
__global__ void k_degrees(const int* __restrict__ src, const int* __restrict__ dst) {
    int e = blockIdx.x * blockDim.x + threadIdx.x;
    if (e >= EE) return;
    atomicAdd(&g_deg_out[src[e]], 1.f);
    atomicAdd(&g_deg_in[dst[e]], 1);
}
// fused: norms + single-pass chained scan (all 49 blocks resident -> safe spin)
__global__ void k_scan_norms() {
    __shared__ int s[1024];
    __shared__ int s_carry;
    int tid = threadIdx.x, b = blockIdx.x;
    int i = b * 1024 + tid;
    if (i < NN) {
        g_norm_out[i] = rsqrtf(fmaxf(g_deg_out[i], 1.f));
        float dmx = fmaxf((float)g_deg_in[i], 1.f);
        g_norm_in[i] = rsqrtf(dmx);
        g_invdeg[i]  = 1.f / dmx;
    }
    int v = (i < NN) ? g_deg_in[i] : 0;
    s[tid] = v;
    __syncthreads();
    for (int off = 1; off < 1024; off <<= 1) {
        int t = (tid >= off) ? s[tid - off] : 0;
        __syncthreads();
        s[tid] += t;
        __syncthreads();
    }
    if (tid == 1023) {
        int prev = 0;
        if (b > 0) {
            int pv;
            do { pv = atomicAdd(&g_pref[b - 1], 0); } while (pv == 0);
            prev = pv - 1;
        }
        atomicExch(&g_pref[b], prev + s[1023] + 1);
        s_carry = prev;
    }
    __syncthreads();
    int carry = s_carry;
    if (i < NN) g_off[i + 1] = s[tid] + carry;
    if (i == 0) g_off[0] = 0;
}
__global__ void k_fill(const int* __restrict__ src, const int* __restrict__ dst) {
    int e = blockIdx.x * blockDim.x + threadIdx.x;
    if (e >= EE) return;
    int d = dst[e];
    int p = atomicAdd(&g_cur[d], 1);
    g_csr[g_off[d] + p] = src[e];
}

// ---------------- fused weight prep ----------------
__device__ __forceinline__ void wsplit(const float* W, int KB, int NB, int KPAD,
                                       __nv_bfloat16* bh, __nv_bfloat16* bl, int idx) {
    int n = idx / KPAD, k = idx % KPAD;
    float v = (n < NB && k < KB) ? W[(size_t)k * NB + n] : 0.f;
    __nv_bfloat16 hv = __float2bfloat16(v);
    bh[idx] = hv;
    bl[idx] = __float2bfloat16(v - __bfloat162float(hv));
}
__global__ void k_wprep_all(const float* __restrict__ W1, const float* __restrict__ Wn,
                            const float* __restrict__ Ws, const float* __restrict__ W3) {
    int i = blockIdx.x * 256 + threadIdx.x;
    const int S1 = 160 * 128, S2 = 128 * 160, S3 = 128 * 160, S4 = 64 * 128;
    if (i < S1) { wsplit(W1, DIN, D1, 128, g_B1h, g_B1l, i); return; }
    i -= S1;
    if (i < S2) { wsplit(Wn, D1, D2, 160, g_BWnh, g_BWnl, i); return; }
    i -= S2;
    if (i < S3) { wsplit(Ws, D1, D2, 160, g_BWsh, g_BWsl, i); return; }
    i -= S3;
    if (i < S4) { wsplit(W3, D2, DOUT, 128, g_B3h, g_B3l, i); return; }
}

// ---------------- layer-1 aggregation -> bf16 hi/lo ----------------
__global__ void k_agg1(const float* __restrict__ x) {
    int w    = (blockIdx.x * blockDim.x + threadIdx.x) >> 5;
    int lane = threadIdx.x & 31;
    if (w >= NN) return;
    int beg = g_off[w], end = g_off[w + 1];
    const float4* X = (const float4*)x;
    float4 acc = make_float4(0.f, 0.f, 0.f, 0.f);
    int j = beg;
    for (; j + 1 < end; j += 2) {
        int s0 = g_csr[j], s1 = g_csr[j + 1];
        float w0 = g_norm_out[s0], w1 = g_norm_out[s1];
        float4 v0 = X[(size_t)s0 * 32 + lane];
        float4 v1 = X[(size_t)s1 * 32 + lane];
        acc.x += v0.x * w0 + v1.x * w1;
        acc.y += v0.y * w0 + v1.y * w1;
        acc.z += v0.z * w0 + v1.z * w1;
        acc.w += v0.w * w0 + v1.w * w1;
    }
    if (j < end) {
        int s0 = g_csr[j];
        float w0 = g_norm_out[s0];
        float4 v0 = X[(size_t)s0 * 32 + lane];
        acc.x += v0.x * w0; acc.y += v0.y * w0; acc.z += v0.z * w0; acc.w += v0.w * w0;
    }
    float ni = g_norm_in[w];
    float v[4] = { acc.x * ni, acc.y * ni, acc.z * ni, acc.w * ni };
    __nv_bfloat16 hv[4], lv[4];
#pragma unroll
    for (int q = 0; q < 4; q++) {
        hv[q] = __float2bfloat16(v[q]);
        lv[q] = __float2bfloat16(v[q] - __bfloat162float(hv[q]));
    }
    *(ushort4*)&g_aggh[(size_t)w * DIN + lane * 4] =
        make_ushort4(__bfloat16_as_ushort(hv[0]), __bfloat16_as_ushort(hv[1]),
                     __bfloat16_as_ushort(hv[2]), __bfloat16_as_ushort(hv[3]));
    *(ushort4*)&g_aggl[(size_t)w * DIN + lane * 4] =
        make_ushort4(__bfloat16_as_ushort(lv[0]), __bfloat16_as_ushort(lv[1]),
                     __bfloat16_as_ushort(lv[2]), __bfloat16_as_ushort(lv[3]));
}

// ---------------- layer-2 aggregation of hWn (fp32, 100 cols = 25 float4) --------
__global__ void k_agg2() {
    int w    = (blockIdx.x * blockDim.x + threadIdx.x) >> 5;
    int lane = threadIdx.x & 31;
    if (w >= NN) return;
    if (lane >= LD2 / 4) return;
    int beg = g_off[w], end = g_off[w + 1];
    const float4* X = (const float4*)g_hWn;
    float4 acc = make_float4(0.f, 0.f, 0.f, 0.f);
    int j = beg;
    for (; j + 1 < end; j += 2) {
        int s0 = g_csr[j], s1 = g_csr[j + 1];
        float4 v0 = X[(size_t)s0 * (LD2 / 4) + lane];
        float4 v1 = X[(size_t)s1 * (LD2 / 4) + lane];
        acc.x += v0.x + v1.x; acc.y += v0.y + v1.y;
        acc.z += v0.z + v1.z; acc.w += v0.w + v1.w;
    }
    if (j < end) {
        int s0 = g_csr[j];
        float4 v0 = X[(size_t)s0 * (LD2 / 4) + lane];
        acc.x += v0.x; acc.y += v0.y; acc.z += v0.z; acc.w += v0.w;
    }
    float inv = g_invdeg[w];
    acc.x *= inv; acc.y *= inv; acc.z *= inv; acc.w *= inv;
    ((float4*)g_neighWn)[(size_t)w * (LD2 / 4) + lane] = acc;
}

// ---------------- fused 3-term bf16-split GEMM (mma.sync) ----------------
// D = Ahi.Bhi + Ahi.Blo + Alo.Bhi ; block 128M x (NWN*32)N, warps 4M x NWN
template<int NWN, int KPAD, bool HAS_EPI, bool HAS_C0, bool OUT_SPLIT>
__global__ void __launch_bounds__(128 * NWN, 2) k_mm(
    const __nv_bfloat16* __restrict__ Ah, const __nv_bfloat16* __restrict__ Al,
    int M,
    const __nv_bfloat16* __restrict__ Bh, const __nv_bfloat16* __restrict__ Bl,
    const float* __restrict__ bias, int NB,
    const float* __restrict__ C0, int ldc0,
    float* __restrict__ Of, __nv_bfloat16* __restrict__ Oh,
    __nv_bfloat16* __restrict__ Ol, int ldo)
{
    constexpr int NT  = NWN * 32;
    constexpr int NC  = KPAD / 32;
    constexpr int ATB = 128 * 80;            // A tile bytes (rows padded to 40 bf16)
    constexpr int BTB = NT * 80;
    __shared__ __align__(16) char smem[2 * ATB + 2 * BTB];
    char* sAH = smem;
    char* sAL = smem + ATB;
    char* sBH = smem + 2 * ATB;
    char* sBL = smem + 2 * ATB + BTB;

    int t = threadIdx.x, lane = t & 31, wid = t >> 5;
    int wm = wid & 3, wn = wid >> 2;
    int m0 = blockIdx.y * 128, n0 = blockIdx.x * NT;

    uint32_t sbase = smem_u32(smem);
    int tile = lane >> 3, trow = lane & 7;
    uint32_t aOff = (uint32_t)(((wm * 32 + (tile & 1) * 8 + trow) * 40 + (tile >> 1) * 8) * 2);
    uint32_t bOff = (uint32_t)(((wn * 32 + (tile >> 1) * 8 + trow) * 40 + (tile & 1) * 8) * 2);
    uint32_t aH_addr = sbase + aOff;
    uint32_t aL_addr = sbase + ATB + aOff;
    uint32_t bH_addr = sbase + 2 * ATB + bOff;
    uint32_t bL_addr = sbase + 2 * ATB + BTB + bOff;

    float d[2][4][4];
#pragma unroll
    for (int i = 0; i < 2; i++)
#pragma unroll
        for (int j = 0; j < 4; j++)
#pragma unroll
            for (int q = 0; q < 4; q++) d[i][j][q] = 0.f;

    // staging registers
    uint4 rah[NWN == 2 ? 2 : 4], ral[NWN == 2 ? 2 : 4];
    uint4 rbh, rbl;
    int arow, ahalf, brow, bq;
    if (NWN == 2) { arow = t >> 1; ahalf = t & 1; brow = t >> 1; bq = t & 1; }
    else          { arow = t;      ahalf = 0;     brow = t >> 2; bq = t & 3; }
    int mload = m0 + arow; if (mload >= M) mload = M - 1;

    auto ldregs = [&](int cc) {
        int k0 = cc * 32;
        if (NWN == 2) {
            const char* ah = (const char*)(Ah + (size_t)mload * KPAD + k0) + ahalf * 32;
            const char* al = (const char*)(Al + (size_t)mload * KPAD + k0) + ahalf * 32;
            rah[0] = *(const uint4*)ah;  rah[1] = *(const uint4*)(ah + 16);
            ral[0] = *(const uint4*)al;  ral[1] = *(const uint4*)(al + 16);
            if (t < 128) {
                int n = n0 + brow;
                const char* bh = (const char*)(Bh + (size_t)n * KPAD + k0) + bq * 32;
                const char* bl = (const char*)(Bl + (size_t)n * KPAD + k0) + bq * 32;
                rbh = *(const uint4*)bh;
                rbl = *(const uint4*)bl;
                // second halves via extra regs: reuse rah trick not possible; load below in store
            }
        } else {
            const char* ah = (const char*)(Ah + (size_t)mload * KPAD + k0);
            const char* al = (const char*)(Al + (size_t)mload * KPAD + k0);
#pragma unroll
            for (int q2 = 0; q2 < 4; q2++) {
                rah[q2] = *(const uint4*)(ah + q2 * 16);
                ral[q2] = *(const uint4*)(al + q2 * 16);
            }
            int n = n0 + brow;
            const char* bh = (const char*)(Bh + (size_t)n * KPAD + k0) + bq * 16;
            const char* bl = (const char*)(Bl + (size_t)n * KPAD + k0) + bq * 16;
            rbh = *(const uint4*)bh;
            rbl = *(const uint4*)bl;
        }
    };
    // NWN==2 B second half loaded separately (kept simple: 2 uint4 per row half)
    uint4 rbh2, rbl2;
    auto ldregsB2 = [&](int cc) {
        if (NWN == 2 && t < 128) {
            int k0 = cc * 32, n = n0 + brow;
            const char* bh = (const char*)(Bh + (size_t)n * KPAD + k0) + bq * 32 + 16;
            const char* bl = (const char*)(Bl + (size_t)n * KPAD + k0) + bq * 32 + 16;
            rbh2 = *(const uint4*)bh;
            rbl2 = *(const uint4*)bl;
        }
    };

    ldregs(0); ldregsB2(0);
#pragma unroll 1
    for (int cc = 0; cc < NC; cc++) {
        __syncthreads();   // prev compute done before overwrite
        if (NWN == 2) {
            char* pah = sAH + arow * 80 + ahalf * 32;
            char* pal = sAL + arow * 80 + ahalf * 32;
            *(uint4*)pah = rah[0]; *(uint4*)(pah + 16) = rah[1];
            *(uint4*)pal = ral[0]; *(uint4*)(pal + 16) = ral[1];
            if (t < 128) {
                char* pbh = sBH + brow * 80 + bq * 32;
                char* pbl = sBL + brow * 80 + bq * 32;
                *(uint4*)pbh = rbh; *(uint4*)(pbh + 16) = rbh2;
                *(uint4*)pbl = rbl; *(uint4*)(pbl + 16) = rbl2;
            }
        } else {
            char* pah = sAH + arow * 80;
            char* pal = sAL + arow * 80;
#pragma unroll
            for (int q2 = 0; q2 < 4; q2++) {
                *(uint4*)(pah + q2 * 16) = rah[q2];
                *(uint4*)(pal + q2 * 16) = ral[q2];
            }
            char* pbh = sBH + brow * 80 + bq * 16;
            char* pbl = sBL + brow * 80 + bq * 16;
            *(uint4*)pbh = rbh;
            *(uint4*)pbl = rbl;
        }
        __syncthreads();
        if (cc + 1 < NC) { ldregs(cc + 1); ldregsB2(cc + 1); }
#pragma unroll
        for (int kk = 0; kk < 2; kk++) {
            uint32_t aH[2][4], aL[2][4], bH[2][4], bL[2][4];
            ldsm_x4(aH_addr + kk * 32, aH[0]);
            ldsm_x4(aH_addr + 1280 + kk * 32, aH[1]);
            ldsm_x4(aL_addr + kk * 32, aL[0]);
            ldsm_x4(aL_addr + 1280 + kk * 32, aL[1]);
            ldsm_x4(bH_addr + kk * 32, bH[0]);
            ldsm_x4(bH_addr + 1280 + kk * 32, bH[1]);
            ldsm_x4(bL_addr + kk * 32, bL[0]);
            ldsm_x4(bL_addr + 1280 + kk * 32, bL[1]);
#pragma unroll
            for (int mf = 0; mf < 2; mf++)
#pragma unroll
                for (int nf = 0; nf < 4; nf++) {
                    uint32_t* bhp = &bH[nf >> 1][(nf & 1) * 2];
                    uint32_t* blp = &bL[nf >> 1][(nf & 1) * 2];
                    mma_bf16(d[mf][nf], aH[mf], bhp);
                    mma_bf16(d[mf][nf], aH[mf], blp);
                    mma_bf16(d[mf][nf], aL[mf], bhp);
                }
        }
    }

    // ---------------- epilogue ----------------
    int rbase = lane >> 2, cpair = (lane & 3) * 2;
    float bv[4][2];
#pragma unroll
    for (int nf = 0; nf < 4; nf++) {
        int c = n0 + wn * 32 + nf * 8 + cpair;
        bv[nf][0] = (HAS_EPI && c < NB) ? bias[c] : 0.f;
        bv[nf][1] = (HAS_EPI && c + 1 < NB) ? bias[c + 1] : 0.f;
    }
#pragma unroll
    for (int mf = 0; mf < 2; mf++) {
#pragma unroll
        for (int h = 0; h < 2; h++) {
            int m = m0 + wm * 32 + mf * 16 + h * 8 + rbase;
            if (m >= M) continue;
#pragma unroll
            for (int nf = 0; nf < 4; nf++) {
                int c = n0 + wn * 32 + nf * 8 + cpair;
                float v0 = d[mf][nf][h * 2 + 0] + bv[nf][0];
                float v1 = d[mf][nf][h * 2 + 1] + bv[nf][1];
                if (HAS_C0) {
                    if (c < ldc0)     v0 += C0[(size_t)m * ldc0 + c];
                    if (c + 1 < ldc0) v1 += C0[(size_t)m * ldc0 + c + 1];
                }
                if (HAS_EPI) { v0 = elu_f(v0); v1 = elu_f(v1); }
                if (OUT_SPLIT) {
                    __nv_bfloat16 h0 = __float2bfloat16(v0);
                    __nv_bfloat16 h1v = __float2bfloat16(v1);
                    __nv_bfloat16 l0 = __float2bfloat16(v0 - __bfloat162float(h0));
                    __nv_bfloat16 l1 = __float2bfloat16(v1 - __bfloat162float(h1v));
                    *(ushort2*)&Oh[(size_t)m * ldo + c] =
                        make_ushort2(__bfloat16_as_ushort(h0), __bfloat16_as_ushort(h1v));
                    *(ushort2*)&Ol[(size_t)m * ldo + c] =
                        make_ushort2(__bfloat16_as_ushort(l0), __bfloat16_as_ushort(l1));
                } else {
                    if (c < ldo)
                        *(float2*)&Of[(size_t)m * ldo + c] = make_float2(v0, v1);
                }
            }
        }
    }
}

// ---------------- launch ----------------
extern "C" void kernel_launch(void* const* d_in, const int* in_sizes, int n_in,
                              void* d_out, int out_size) {
    const float* x   = (const float*)d_in[0];
    const int*   src = (const int*)d_in[1];
    const int*   dst = (const int*)d_in[2];
    const float* W1  = (const float*)d_in[3];
    const float* b1  = (const float*)d_in[4];
    const float* Wn  = (const float*)d_in[5];
    const float* Ws  = (const float*)d_in[6];
    const float* b2  = (const float*)d_in[7];
    const float* W3  = (const float*)d_in[8];
    const float* b3  = (const float*)d_in[9];
    float* out = (float*)d_out;

    auto sym = [](const void* s) { void* p = nullptr; cudaGetSymbolAddress(&p, s); return p; };
    __nv_bfloat16* aggh = (__nv_bfloat16*)sym(g_aggh);
    __nv_bfloat16* aggl = (__nv_bfloat16*)sym(g_aggl);
    __nv_bfloat16* h1h  = (__nv_bfloat16*)sym(g_h1h);
    __nv_bfloat16* h1l  = (__nv_bfloat16*)sym(g_h1l);
    __nv_bfloat16* h2h  = (__nv_bfloat16*)sym(g_h2h);
    __nv_bfloat16* h2l  = (__nv_bfloat16*)sym(g_h2l);
    float* hWn    = (float*)sym(g_hWn);
    float* neighW = (float*)sym(g_neighWn);
    __nv_bfloat16* B1h  = (__nv_bfloat16*)sym(g_B1h),  *B1l  = (__nv_bfloat16*)sym(g_B1l);
    __nv_bfloat16* BWnh = (__nv_bfloat16*)sym(g_BWnh), *BWnl = (__nv_bfloat16*)sym(g_BWnl);
    __nv_bfloat16* BWsh = (__nv_bfloat16*)sym(g_BWsh), *BWsl = (__nv_bfloat16*)sym(g_BWsl);
    __nv_bfloat16* B3h  = (__nv_bfloat16*)sym(g_B3h),  *B3l  = (__nv_bfloat16*)sym(g_B3l);

    k_zero<<<(NN + 255) / 256, 256>>>();
    k_degrees<<<(EE + 255) / 256, 256>>>(src, dst);
    k_scan_norms<<<SCAN_B, 1024>>>();
    k_fill<<<(EE + 255) / 256, 256>>>(src, dst);          // <- profiled slot
    k_wprep_all<<<(160*128 + 128*160*2 + 64*128 + 255) / 256, 256>>>(W1, Wn, Ws, W3);

    int agg_blocks = (NN * 32 + 255) / 256;
    k_agg1<<<agg_blocks, 256>>>(x);

    int MT = (NN + 127) / 128;  // 391

    // h1 = elu(agg @ W1 + b1) -> bf16 hi/lo [NN, 160]
    k_mm<1, 128, true, false, true><<<dim3(5, MT), 128>>>(
        aggh, aggl, NN, B1h, B1l, b1, D1, nullptr, 0,
        nullptr, h1h, h1l, KP1);

    // hWn = h1 @ Wn -> fp32 [NN, 100]
    k_mm<2, 160, false, false, false><<<dim3(2, MT), 256>>>(
        h1h, h1l, NN, BWnh, BWnl, nullptr, 0, nullptr, 0,
        hWn, nullptr, nullptr, LD2);

    k_agg2<<<agg_blocks, 256>>>();

    // h2 = elu(h1 @ Ws + neighWn + b2) -> bf16 hi/lo [NN, 128]
    k_mm<2, 160, true, true, true><<<dim3(2, MT), 256>>>(
        h1h, h1l, NN, BWsh, BWsl, b2, D2, neighW, LD2,
        nullptr, h2h, h2l, KP2);

    // out = elu(h2 @ W3 + b3) -> fp32 [NN, 64]
    k_mm<2, 128, true, false, false><<<dim3(1, MT), 256>>>(
        h2h, h2l, NN, B3h, B3l, b3, DOUT, nullptr, 0,
        out, nullptr, nullptr, DOUT);
}

// round 7
// speedup vs baseline: 1.5139x; 1.0148x over previous
#include <cuda_runtime.h>
#include <cuda_bf16.h>
#include <math.h>
#include <stdint.h>

#define NN   50000
#define EE   800000
#define DIN  128
#define D1   150
#define KP1  160     // h1 K-padded (5 chunks of 32)
#define D2   100
#define LD2  100     // fp32 hWn/neighWn stride
#define KP2  128     // h2 K-padded
#define DOUT 64
#define SCAN_B ((NN + 1023) / 1024)

// ---------------- scratch ----------------
__device__ float g_deg_out[NN];
__device__ int   g_deg_in[NN];
__device__ int   g_off[NN + 1];
__device__ int   g_cur[NN];
__device__ int   g_pref[SCAN_B];
__device__ int   g_csr[EE];
__device__ float g_norm_out[NN];
__device__ float g_norm_in[NN];
__device__ float g_invdeg[NN];

__device__ __align__(16) __nv_bfloat16 g_aggh[(size_t)NN * DIN];
__device__ __align__(16) __nv_bfloat16 g_aggl[(size_t)NN * DIN];
__device__ __align__(16) __nv_bfloat16 g_h1h[(size_t)NN * KP1];
__device__ __align__(16) __nv_bfloat16 g_h1l[(size_t)NN * KP1];
__device__ __align__(16) __nv_bfloat16 g_h2h[(size_t)NN * KP2];
__device__ __align__(16) __nv_bfloat16 g_h2l[(size_t)NN * KP2];
__device__ __align__(16) float g_hWn[(size_t)NN * LD2];
__device__ __align__(16) float g_neighWn[(size_t)NN * LD2];

// weights transposed [NPAD, KPAD] bf16 hi/lo
__device__ __align__(16) __nv_bfloat16 g_B1h[160 * 128], g_B1l[160 * 128];
__device__ __align__(16) __nv_bfloat16 g_BWnh[128 * 160], g_BWnl[128 * 160];
__device__ __align__(16) __nv_bfloat16 g_BWsh[128 * 160], g_BWsl[128 * 160];
__device__ __align__(16) __nv_bfloat16 g_B3h[64 * 128],  g_B3l[64 * 128];

__device__ __forceinline__ float elu_f(float v) { return v > 0.f ? v : expm1f(v); }

__device__ __forceinline__ uint32_t smem_u32(const void* p) {
    uint32_t a;
    asm("{ .reg .u64 t; cvta.to.shared.u64 t, %1; cvt.u32.u64 %0, t; }" : "=r"(a) : "l"(p));
    return a;
}
__device__ __forceinline__ void ldsm_x4(uint32_t addr, uint32_t* r) {
    asm volatile("ldmatrix.sync.aligned.m8n8.x4.shared.b16 {%0,%1,%2,%3}, [%4];"
                 : "=r"(r[0]), "=r"(r[1]), "=r"(r[2]), "=r"(r[3]) : "r"(addr));
}
__device__ __forceinline__ void mma_bf16(float* d, const uint32_t* a, const uint32_t* b) {
    asm volatile("mma.sync.aligned.m16n8k16.row.col.f32.bf16.bf16.f32 "
                 "{%0,%1,%2,%3}, {%4,%5,%6,%7}, {%8,%9}, {%0,%1,%2,%3};"
                 : "+f"(d[0]), "+f"(d[1]), "+f"(d[2]), "+f"(d[3])
                 : "r"(a[0]), "r"(a[1]), "r"(a[2]), "r"(a[3]), "r"(b[0]), "r"(b[1]));
}

// ---------------- preprocessing ----------------
__global__ void k_zero() {
    int i = blockIdx.x * blockDim.x + threadIdx.x;
    if (i < NN) { g_deg_out[i] = 0.f; g_deg_in[i] = 0; g_cur[i] = 0; }
    if (i < SCAN_B) g_pref[i] = 0;
}
// 4 edges/thread via int4 -> MLP 4
__global__ void k_degrees(const int4* __restrict__ src4, const int4* __restrict__ dst4) {
    int i = blockIdx.x * blockDim.x + threadIdx.x;
    if (i >= EE / 4) return;
    int4 s = src4[i], d = dst4[i];
    atomicAdd(&g_deg_out[s.x], 1.f);
    atomicAdd(&g_deg_out[s.y], 1.f);
    atomicAdd(&g_deg_out[s.z], 1.f);
    atomicAdd(&g_deg_out[s.w], 1.f);
    atomicAdd(&g_deg_in[d.x], 1);
    atomicAdd(&g_deg_in[d.y], 1);
    atomicAdd(&g_deg_in[d.z], 1);
    atomicAdd(&g_deg_in[d.w], 1);
}
// fused: norms + single-pass chained scan (all 49 blocks resident -> safe spin)
__global__ void k_scan_norms() {
    __shared__ int s[1024];
    __shared__ int s_carry;
    int tid = threadIdx.x, b = blockIdx.x;
    int i = b * 1024 + tid;
    if (i < NN) {
        g_norm_out[i] = rsqrtf(fmaxf(g_deg_out[i], 1.f));
        float dmx = fmaxf((float)g_deg_in[i], 1.f);
        g_norm_in[i] = rsqrtf(dmx);
        g_invdeg[i]  = 1.f / dmx;
    }
    int v = (i < NN) ? g_deg_in[i] : 0;
    s[tid] = v;
    __syncthreads();
    for (int off = 1; off < 1024; off <<= 1) {
        int t = (tid >= off) ? s[tid - off] : 0;
        __syncthreads();
        s[tid] += t;
        __syncthreads();
    }
    if (tid == 1023) {
        int prev = 0;
        if (b > 0) {
            int pv;
            do { pv = atomicAdd(&g_pref[b - 1], 0); } while (pv == 0);
            prev = pv - 1;
        }
        atomicExch(&g_pref[b], prev + s[1023] + 1);
        s_carry = prev;
    }
    __syncthreads();
    int carry = s_carry;
    if (i < NN) g_off[i + 1] = s[tid] + carry;
    if (i == 0) g_off[0] = 0;
}
// 4 edges/thread via int4 -> 4 independent atomic->store chains
__global__ void k_fill(const int4* __restrict__ src4, const int4* __restrict__ dst4) {
    int i = blockIdx.x * blockDim.x + threadIdx.x;
    if (i >= EE / 4) return;
    int4 s = src4[i], d = dst4[i];
    int p0 = atomicAdd(&g_cur[d.x], 1);
    int p1 = atomicAdd(&g_cur[d.y], 1);
    int p2 = atomicAdd(&g_cur[d.z], 1);
    int p3 = atomicAdd(&g_cur[d.w], 1);
    g_csr[g_off[d.x] + p0] = s.x;
    g_csr[g_off[d.y] + p1] = s.y;
    g_csr[g_off[d.z] + p2] = s.z;
    g_csr[g_off[d.w] + p3] = s.w;
}

// ---------------- fused weight prep ----------------
__device__ __forceinline__ void wsplit(const float* W, int KB, int NB, int KPAD,
                                       __nv_bfloat16* bh, __nv_bfloat16* bl, int idx) {
    int n = idx / KPAD, k = idx % KPAD;
    float v = (n < NB && k < KB) ? W[(size_t)k * NB + n] : 0.f;
    __nv_bfloat16 hv = __float2bfloat16(v);
    bh[idx] = hv;
    bl[idx] = __float2bfloat16(v - __bfloat162float(hv));
}
__global__ void k_wprep_all(const float* __restrict__ W1, const float* __restrict__ Wn,
                            const float* __restrict__ Ws, const float* __restrict__ W3) {
    int i = blockIdx.x * 256 + threadIdx.x;
    const int S1 = 160 * 128, S2 = 128 * 160, S3 = 128 * 160, S4 = 64 * 128;
    if (i < S1) { wsplit(W1, DIN, D1, 128, g_B1h, g_B1l, i); return; }
    i -= S1;
    if (i < S2) { wsplit(Wn, D1, D2, 160, g_BWnh, g_BWnl, i); return; }
    i -= S2;
    if (i < S3) { wsplit(Ws, D1, D2, 160, g_BWsh, g_BWsl, i); return; }
    i -= S3;
    if (i < S4) { wsplit(W3, D2, DOUT, 128, g_B3h, g_B3l, i); return; }
}

// ---------------- layer-1 aggregation -> bf16 hi/lo (4-edge unrolled) -----------
__global__ void k_agg1(const float* __restrict__ x) {
    int w    = (blockIdx.x * blockDim.x + threadIdx.x) >> 5;
    int lane = threadIdx.x & 31;
    if (w >= NN) return;
    int beg = g_off[w], end = g_off[w + 1];
    const float4* X = (const float4*)x;
    float4 acc = make_float4(0.f, 0.f, 0.f, 0.f);
    int j = beg;
    for (; j + 3 < end; j += 4) {
        int s0 = g_csr[j], s1 = g_csr[j + 1], s2 = g_csr[j + 2], s3 = g_csr[j + 3];
        float w0 = g_norm_out[s0], w1 = g_norm_out[s1];
        float w2 = g_norm_out[s2], w3 = g_norm_out[s3];
        float4 v0 = X[(size_t)s0 * 32 + lane];
        float4 v1 = X[(size_t)s1 * 32 + lane];
        float4 v2 = X[(size_t)s2 * 32 + lane];
        float4 v3 = X[(size_t)s3 * 32 + lane];
        acc.x += v0.x * w0 + v1.x * w1 + v2.x * w2 + v3.x * w3;
        acc.y += v0.y * w0 + v1.y * w1 + v2.y * w2 + v3.y * w3;
        acc.z += v0.z * w0 + v1.z * w1 + v2.z * w2 + v3.z * w3;
        acc.w += v0.w * w0 + v1.w * w1 + v2.w * w2 + v3.w * w3;
    }
    for (; j < end; j++) {
        int s0 = g_csr[j];
        float w0 = g_norm_out[s0];
        float4 v0 = X[(size_t)s0 * 32 + lane];
        acc.x += v0.x * w0; acc.y += v0.y * w0; acc.z += v0.z * w0; acc.w += v0.w * w0;
    }
    float ni = g_norm_in[w];
    float v[4] = { acc.x * ni, acc.y * ni, acc.z * ni, acc.w * ni };
    __nv_bfloat16 hv[4], lv[4];
#pragma unroll
    for (int q = 0; q < 4; q++) {
        hv[q] = __float2bfloat16(v[q]);
        lv[q] = __float2bfloat16(v[q] - __bfloat162float(hv[q]));
    }
    *(ushort4*)&g_aggh[(size_t)w * DIN + lane * 4] =
        make_ushort4(__bfloat16_as_ushort(hv[0]), __bfloat16_as_ushort(hv[1]),
                     __bfloat16_as_ushort(hv[2]), __bfloat16_as_ushort(hv[3]));
    *(ushort4*)&g_aggl[(size_t)w * DIN + lane * 4] =
        make_ushort4(__bfloat16_as_ushort(lv[0]), __bfloat16_as_ushort(lv[1]),
                     __bfloat16_as_ushort(lv[2]), __bfloat16_as_ushort(lv[3]));
}

// ---------------- layer-2 aggregation of hWn (fp32, 100 cols = 25 float4) --------
__global__ void k_agg2() {
    int w    = (blockIdx.x * blockDim.x + threadIdx.x) >> 5;
    int lane = threadIdx.x & 31;
    if (w >= NN) return;
    if (lane >= LD2 / 4) return;
    int beg = g_off[w], end = g_off[w + 1];
    const float4* X = (const float4*)g_hWn;
    float4 acc = make_float4(0.f, 0.f, 0.f, 0.f);
    int j = beg;
    for (; j + 1 < end; j += 2) {
        int s0 = g_csr[j], s1 = g_csr[j + 1];
        float4 v0 = X[(size_t)s0 * (LD2 / 4) + lane];
        float4 v1 = X[(size_t)s1 * (LD2 / 4) + lane];
        acc.x += v0.x + v1.x; acc.y += v0.y + v1.y;
        acc.z += v0.z + v1.z; acc.w += v0.w + v1.w;
    }
    if (j < end) {
        int s0 = g_csr[j];
        float4 v0 = X[(size_t)s0 * (LD2 / 4) + lane];
        acc.x += v0.x; acc.y += v0.y; acc.z += v0.z; acc.w += v0.w;
    }
    float inv = g_invdeg[w];
    acc.x *= inv; acc.y *= inv; acc.z *= inv; acc.w *= inv;
    ((float4*)g_neighWn)[(size_t)w * (LD2 / 4) + lane] = acc;
}

// ---------------- fused 3-term bf16-split GEMM with frag skipping ----------------
// D = Ahi.Bhi + Ahi.Blo + Alo.Bhi ; block 128M x (NWN*32)N, warps 4M x NWN
// n8 fragments whose column base >= NB are skipped (warp-uniform predicate).
template<int NWN, int KPAD, bool HAS_EPI, bool HAS_C0, bool OUT_SPLIT>
__global__ void __launch_bounds__(128 * NWN, 2) k_mm(
    const __nv_bfloat16* __restrict__ Ah, const __nv_bfloat16* __restrict__ Al,
    int M,
    const __nv_bfloat16* __restrict__ Bh, const __nv_bfloat16* __restrict__ Bl,
    const float* __restrict__ bias, int NB,
    const float* __restrict__ C0, int ldc0,
    float* __restrict__ Of, __nv_bfloat16* __restrict__ Oh,
    __nv_bfloat16* __restrict__ Ol, int ldo)
{
    constexpr int NT  = NWN * 32;
    constexpr int NC  = KPAD / 32;
    constexpr int ATB = 128 * 80;            // A tile bytes (rows padded to 40 bf16)
    constexpr int BTB = NT * 80;
    __shared__ __align__(16) char smem[2 * ATB + 2 * BTB];
    char* sAH = smem;
    char* sAL = smem + ATB;
    char* sBH = smem + 2 * ATB;
    char* sBL = smem + 2 * ATB + BTB;

    int t = threadIdx.x, lane = t & 31, wid = t >> 5;
    int wm = wid & 3, wn = wid >> 2;
    int m0 = blockIdx.y * 128, n0 = blockIdx.x * NT;

    // warp-uniform fragment activity
    int cw = n0 + wn * 32;
    bool act0 = (cw + 0)  < NB;
    bool act1 = (cw + 8)  < NB;
    bool act2 = (cw + 16) < NB;
    bool act3 = (cw + 24) < NB;
    bool act23 = act2 | act3;

    uint32_t sbase = smem_u32(smem);
    int tile = lane >> 3, trow = lane & 7;
    uint32_t aOff = (uint32_t)(((wm * 32 + (tile & 1) * 8 + trow) * 40 + (tile >> 1) * 8) * 2);
    uint32_t bOff = (uint32_t)(((wn * 32 + (tile >> 1) * 8 + trow) * 40 + (tile & 1) * 8) * 2);
    uint32_t aH_addr = sbase + aOff;
    uint32_t aL_addr = sbase + ATB + aOff;
    uint32_t bH_addr = sbase + 2 * ATB + bOff;
    uint32_t bL_addr = sbase + 2 * ATB + BTB + bOff;

    float d[2][4][4];
#pragma unroll
    for (int i = 0; i < 2; i++)
#pragma unroll
        for (int j = 0; j < 4; j++)
#pragma unroll
            for (int q = 0; q < 4; q++) d[i][j][q] = 0.f;

    // staging registers
    uint4 rah[NWN == 2 ? 2 : 4], ral[NWN == 2 ? 2 : 4];
    uint4 rbh, rbl;
    int arow, ahalf, brow, bq;
    if (NWN == 2) { arow = t >> 1; ahalf = t & 1; brow = t >> 1; bq = t & 1; }
    else          { arow = t;      ahalf = 0;     brow = t >> 2; bq = t & 3; }
    int mload = m0 + arow; if (mload >= M) mload = M - 1;

    auto ldregs = [&](int cc) {
        int k0 = cc * 32;
        if (NWN == 2) {
            const char* ah = (const char*)(Ah + (size_t)mload * KPAD + k0) + ahalf * 32;
            const char* al = (const char*)(Al + (size_t)mload * KPAD + k0) + ahalf * 32;
            rah[0] = *(const uint4*)ah;  rah[1] = *(const uint4*)(ah + 16);
            ral[0] = *(const uint4*)al;  ral[1] = *(const uint4*)(al + 16);
            if (t < 128) {
                int n = n0 + brow;
                const char* bh = (const char*)(Bh + (size_t)n * KPAD + k0) + bq * 32;
                const char* bl = (const char*)(Bl + (size_t)n * KPAD + k0) + bq * 32;
                rbh = *(const uint4*)bh;
                rbl = *(const uint4*)bl;
            }
        } else {
            const char* ah = (const char*)(Ah + (size_t)mload * KPAD + k0);
            const char* al = (const char*)(Al + (size_t)mload * KPAD + k0);
#pragma unroll
            for (int q2 = 0; q2 < 4; q2++) {
                rah[q2] = *(const uint4*)(ah + q2 * 16);
                ral[q2] = *(const uint4*)(al + q2 * 16);
            }
            int n = n0 + brow;
            const char* bh = (const char*)(Bh + (size_t)n * KPAD + k0) + bq * 16;
            const char* bl = (const char*)(Bl + (size_t)n * KPAD + k0) + bq * 16;
            rbh = *(const uint4*)bh;
            rbl = *(const uint4*)bl;
        }
    };
    uint4 rbh2, rbl2;
    auto ldregsB2 = [&](int cc) {
        if (NWN == 2 && t < 128) {
            int k0 = cc * 32, n = n0 + brow;
            const char* bh = (const char*)(Bh + (size_t)n * KPAD + k0) + bq * 32 + 16;
            const char* bl = (const char*)(Bl + (size_t)n * KPAD + k0) + bq * 32 + 16;
            rbh2 = *(const uint4*)bh;
            rbl2 = *(const uint4*)bl;
        }
    };

    ldregs(0); ldregsB2(0);
#pragma unroll 1
    for (int cc = 0; cc < NC; cc++) {
        __syncthreads();   // prev compute done before overwrite
        if (NWN == 2) {
            char* pah = sAH + arow * 80 + ahalf * 32;
            char* pal = sAL + arow * 80 + ahalf * 32;
            *(uint4*)pah = rah[0]; *(uint4*)(pah + 16) = rah[1];
            *(uint4*)pal = ral[0]; *(uint4*)(pal + 16) = ral[1];
            if (t < 128) {
                char* pbh = sBH + brow * 80 + bq * 32;
                char* pbl = sBL + brow * 80 + bq * 32;
                *(uint4*)pbh = rbh; *(uint4*)(pbh + 16) = rbh2;
                *(uint4*)pbl = rbl; *(uint4*)(pbl + 16) = rbl2;
            }
        } else {
            char* pah = sAH + arow * 80;
            char* pal = sAL + arow * 80;
#pragma unroll
            for (int q2 = 0; q2 < 4; q2++) {
                *(uint4*)(pah + q2 * 16) = rah[q2];
                *(uint4*)(pal + q2 * 16) = ral[q2];
            }
            char* pbh = sBH + brow * 80 + bq * 16;
            char* pbl = sBL + brow * 80 + bq * 16;
            *(uint4*)pbh = rbh;
            *(uint4*)pbl = rbl;
        }
        __syncthreads();
        if (cc + 1 < NC) { ldregs(cc + 1); ldregsB2(cc + 1); }
#pragma unroll
        for (int kk = 0; kk < 2; kk++) {
            uint32_t aH[2][4], aL[2][4], bH[2][4], bL[2][4];
            ldsm_x4(aH_addr + kk * 32, aH[0]);
            ldsm_x4(aH_addr + 1280 + kk * 32, aH[1]);
            ldsm_x4(aL_addr + kk * 32, aL[0]);
            ldsm_x4(aL_addr + 1280 + kk * 32, aL[1]);
            ldsm_x4(bH_addr + kk * 32, bH[0]);
            ldsm_x4(bL_addr + kk * 32, bL[0]);
            if (act23) {
                ldsm_x4(bH_addr + 1280 + kk * 32, bH[1]);
                ldsm_x4(bL_addr + 1280 + kk * 32, bL[1]);
            }
#pragma unroll
            for (int mf = 0; mf < 2; mf++) {
#pragma unroll
                for (int nf = 0; nf < 4; nf++) {
                    bool act = (nf == 0) ? act0 : (nf == 1) ? act1 : (nf == 2) ? act2 : act3;
                    if (act) {
                        uint32_t* bhp = &bH[nf >> 1][(nf & 1) * 2];
                        uint32_t* blp = &bL[nf >> 1][(nf & 1) * 2];
                        mma_bf16(d[mf][nf], aH[mf], bhp);
                        mma_bf16(d[mf][nf], aH[mf], blp);
                        mma_bf16(d[mf][nf], aL[mf], bhp);
                    }
                }
            }
        }
    }

    // ---------------- epilogue ----------------
    int rbase = lane >> 2, cpair = (lane & 3) * 2;
    float bv[4][2];
#pragma unroll
    for (int nf = 0; nf < 4; nf++) {
        int c = n0 + wn * 32 + nf * 8 + cpair;
        bv[nf][0] = (HAS_EPI && c < NB) ? bias[c] : 0.f;
        bv[nf][1] = (HAS_EPI && c + 1 < NB) ? bias[c + 1] : 0.f;
    }
#pragma unroll
    for (int mf = 0; mf < 2; mf++) {
#pragma unroll
        for (int h = 0; h < 2; h++) {
            int m = m0 + wm * 32 + mf * 16 + h * 8 + rbase;
            if (m >= M) continue;
#pragma unroll
            for (int nf = 0; nf < 4; nf++) {
                int c = n0 + wn * 32 + nf * 8 + cpair;
                float v0 = d[mf][nf][h * 2 + 0] + bv[nf][0];
                float v1 = d[mf][nf][h * 2 + 1] + bv[nf][1];
                if (HAS_C0) {
                    if (c < ldc0)     v0 += C0[(size_t)m * ldc0 + c];
                    if (c + 1 < ldc0) v1 += C0[(size_t)m * ldc0 + c + 1];
                }
                if (HAS_EPI) { v0 = elu_f(v0); v1 = elu_f(v1); }
                if (OUT_SPLIT) {
                    __nv_bfloat16 h0 = __float2bfloat16(v0);
                    __nv_bfloat16 h1v = __float2bfloat16(v1);
                    __nv_bfloat16 l0 = __float2bfloat16(v0 - __bfloat162float(h0));
                    __nv_bfloat16 l1 = __float2bfloat16(v1 - __bfloat162float(h1v));
                    *(ushort2*)&Oh[(size_t)m * ldo + c] =
                        make_ushort2(__bfloat16_as_ushort(h0), __bfloat16_as_ushort(h1v));
                    *(ushort2*)&Ol[(size_t)m * ldo + c] =
                        make_ushort2(__bfloat16_as_ushort(l0), __bfloat16_as_ushort(l1));
                } else {
                    if (c < ldo)
                        *(float2*)&Of[(size_t)m * ldo + c] = make_float2(v0, v1);
                }
            }
        }
    }
}

// ---------------- launch ----------------
extern "C" void kernel_launch(void* const* d_in, const int* in_sizes, int n_in,
                              void* d_out, int out_size) {
    const float* x   = (const float*)d_in[0];
    const int*   src = (const int*)d_in[1];
    const int*   dst = (const int*)d_in[2];
    const float* W1  = (const float*)d_in[3];
    const float* b1  = (const float*)d_in[4];
    const float* Wn  = (const float*)d_in[5];
    const float* Ws  = (const float*)d_in[6];
    const float* b2  = (const float*)d_in[7];
    const float* W3  = (const float*)d_in[8];
    const float* b3  = (const float*)d_in[9];
    float* out = (float*)d_out;

    auto sym = [](const void* s) { void* p = nullptr; cudaGetSymbolAddress(&p, s); return p; };
    __nv_bfloat16* aggh = (__nv_bfloat16*)sym(g_aggh);
    __nv_bfloat16* aggl = (__nv_bfloat16*)sym(g_aggl);
    __nv_bfloat16* h1h  = (__nv_bfloat16*)sym(g_h1h);
    __nv_bfloat16* h1l  = (__nv_bfloat16*)sym(g_h1l);
    __nv_bfloat16* h2h  = (__nv_bfloat16*)sym(g_h2h);
    __nv_bfloat16* h2l  = (__nv_bfloat16*)sym(g_h2l);
    float* hWn    = (float*)sym(g_hWn);
    float* neighW = (float*)sym(g_neighWn);
    __nv_bfloat16* B1h  = (__nv_bfloat16*)sym(g_B1h),  *B1l  = (__nv_bfloat16*)sym(g_B1l);
    __nv_bfloat16* BWnh = (__nv_bfloat16*)sym(g_BWnh), *BWnl = (__nv_bfloat16*)sym(g_BWnl);
    __nv_bfloat16* BWsh = (__nv_bfloat16*)sym(g_BWsh), *BWsl = (__nv_bfloat16*)sym(g_BWsl);
    __nv_bfloat16* B3h  = (__nv_bfloat16*)sym(g_B3h),  *B3l  = (__nv_bfloat16*)sym(g_B3l);

    k_zero<<<(NN + 255) / 256, 256>>>();
    k_degrees<<<(EE / 4 + 255) / 256, 256>>>((const int4*)src, (const int4*)dst);
    k_scan_norms<<<SCAN_B, 1024>>>();
    k_fill<<<(EE / 4 + 255) / 256, 256>>>((const int4*)src, (const int4*)dst);
    k_wprep_all<<<(160*128 + 128*160*2 + 64*128 + 255) / 256, 256>>>(W1, Wn, Ws, W3);

    int agg_blocks = (NN * 32 + 255) / 256;
    k_agg1<<<agg_blocks, 256>>>(x);

    int MT = (NN + 127) / 128;  // 391

    // h1 = elu(agg @ W1 + b1) -> bf16 hi/lo [NN, 160]
    k_mm<1, 128, true, false, true><<<dim3(5, MT), 128>>>(
        aggh, aggl, NN, B1h, B1l, b1, D1, nullptr, 0,
        nullptr, h1h, h1l, KP1);

    // hWn = h1 @ Wn -> fp32 [NN, 100]
    k_mm<2, 160, false, false, false><<<dim3(2, MT), 256>>>(
        h1h, h1l, NN, BWnh, BWnl, nullptr, D2, nullptr, 0,
        hWn, nullptr, nullptr, LD2);

    k_agg2<<<agg_blocks, 256>>>();

    // h2 = elu(h1 @ Ws + neighWn + b2) -> bf16 hi/lo [NN, 128]
    k_mm<2, 160, true, true, true><<<dim3(2, MT), 256>>>(
        h1h, h1l, NN, BWsh, BWsl, b2, D2, neighW, LD2,
        nullptr, h2h, h2l, KP2);

    // out = elu(h2 @ W3 + b3) -> fp32 [NN, 64]
    k_mm<2, 128, true, false, false><<<dim3(1, MT), 256>>>(
        h2h, h2l, NN, B3h, B3l, b3, DOUT, nullptr, 0,
        out, nullptr, nullptr, DOUT);
}